// round 17
// baseline (speedup 1.0000x reference)
#include <cuda_runtime.h>
#include <stdint.h>
#include <math.h>

#define NTOK 16384
#define HD   4096
#define NE   64
#define NP   6
#define TK   8

#define CWARPS   8
#define NTHREADS ((CWARPS + 1) * 32)    // 288
#define PROD_WARP CWARPS
#define SLICE    (HD / CWARPS)          // 512 columns per consumer warp

#define UNIT_TOK  8
#define NUNITS    (NTOK / UNIT_TOK)     // 2048
#define STAGE_TOK 2
#define STAGE_BYTES (STAGE_TOK * HD * 4)   // 32768
#define NSPLIT    4
#define SPLIT_BYTES (STAGE_BYTES / NSPLIT) // 8192
#define STAGES    3
#define CPU       (UNIT_TOK / STAGE_TOK)   // 4 chunks per unit
#define GRID      296                       // 2 CTAs per SM
#define BIGCTAS   (NUNITS - GRID * (NUNITS / GRID))   // 272 CTAs take 7 units

// smem byte offsets
#define XS_OFF    0
#define PART_OFF  (STAGES * STAGE_BYTES)                 // 98304
#define PART_ROWS ((UNIT_TOK + 1) * NP)                  // 54
#define PART_SZ   (PART_ROWS * 32 * 4)                   // 6912
#define CENT_OFF  (PART_OFF + PART_SZ)
#define CENTN_OFF (CENT_OFF + NE * NP * 4)
#define MBAR_OFF  ((CENTN_OFF + NE * 4 + 7) & ~7)
#define SMEM_BYTES (MBAR_OFF + 64)                        // ~104.6 KB per CTA

#define FMA2(acc, a, b) \
    asm("fma.rn.f32x2 %0, %1, %2, %0;" : "+l"(acc) : "l"(a), "l"(b))
#define ADD2(d, a, b) \
    asm("add.rn.f32x2 %0, %1, %2;" : "=l"(d) : "l"(a), "l"(b))

__device__ __forceinline__ uint32_t smem_u32(const void* p) {
    uint32_t a;
    asm("{ .reg .u64 t; cvta.to.shared.u64 t, %1; cvt.u32.u64 %0, t; }" : "=r"(a) : "l"(p));
    return a;
}

#define MBAR_INIT(addr, cnt) \
    asm volatile("mbarrier.init.shared.b64 [%0], %1;" :: "r"(addr), "r"(cnt) : "memory")
#define MBAR_EXPECT_TX(addr, bytes) \
    asm volatile("mbarrier.arrive.expect_tx.shared.b64 _, [%0], %1;" :: "r"(addr), "r"(bytes) : "memory")
#define MBAR_ARRIVE(addr) \
    asm volatile("mbarrier.arrive.shared.b64 _, [%0];" :: "r"(addr) : "memory")
#define MBAR_WAIT(addr, parity) do {                                             \
    asm volatile("{\n\t.reg .pred P;\n"                                          \
        "W_%=:\n\tmbarrier.try_wait.parity.acquire.cta.shared::cta.b64 P, [%0], %1, 0x989680;\n" \
        "\t@P bra D_%=;\n\tbra W_%=;\nD_%=:\n\t}"                                \
        :: "r"(addr), "r"(parity) : "memory"); } while (0)

__device__ __forceinline__ void bulk_g2s(uint32_t dst, const void* src,
                                         uint32_t bytes, uint32_t mbar) {
    asm volatile(
        "cp.async.bulk.shared::cta.global.mbarrier::complete_tx::bytes "
        "[%0], [%1], %2, [%3];"
        :: "r"(dst), "l"(src), "r"(bytes), "r"(mbar) : "memory");
}

#define CBAR() asm volatile("bar.sync 1, 256;" ::: "memory")   // consumers only

// one token's 512-col slice partial: XP = ull2* at (token row + warp*SLICE)
#define TOKEN_COMPUTE512(XP, LTOK) do {                                               \
    unsigned long long acc_[NP];                                                      \
    _Pragma("unroll")                                                                 \
    for (int p_ = 0; p_ < NP; p_++) acc_[p_] = 0ull;                                  \
    _Pragma("unroll")                                                                 \
    for (int b_ = 0; b_ < 4; b_++) {                                                  \
        ulonglong2 xv_ = (XP)[b_ * 32 + lane];                                        \
        _Pragma("unroll")                                                             \
        for (int p_ = 0; p_ < NP; p_++) {                                             \
            FMA2(acc_[p_], xv_.x, cA[p_*4 + b_].x);                                   \
            FMA2(acc_[p_], xv_.y, cA[p_*4 + b_].y);                                   \
        }                                                                             \
    }                                                                                 \
    unsigned long long u_[3];                                                         \
    _Pragma("unroll")                                                                 \
    for (int j_ = 0; j_ < 3; j_++) {                                                  \
        float f0_ = __uint_as_float((unsigned)(acc_[2*j_]   & 0xffffffffull)) +       \
                    __uint_as_float((unsigned)(acc_[2*j_]   >> 32));                  \
        float f1_ = __uint_as_float((unsigned)(acc_[2*j_+1] & 0xffffffffull)) +       \
                    __uint_as_float((unsigned)(acc_[2*j_+1] >> 32));                  \
        u_[j_] = ((unsigned long long)__float_as_uint(f1_) << 32) | __float_as_uint(f0_); \
    }                                                                                 \
    _Pragma("unroll")                                                                 \
    for (int o_ = 16; o_ >= 2; o_ >>= 1)                                              \
        _Pragma("unroll")                                                             \
        for (int j_ = 0; j_ < 3; j_++) {                                              \
            unsigned long long v_ = __shfl_xor_sync(0xffffffffu, u_[j_], o_);         \
            ADD2(u_[j_], u_[j_], v_);                                                 \
        }                                                                             \
    if (lane < 2) {                                                                   \
        int slot_ = warp * 2 + lane;                                                  \
        _Pragma("unroll")                                                             \
        for (int j_ = 0; j_ < 3; j_++) {                                              \
            part[((LTOK)*NP + 2*j_  )*32 + slot_] = __uint_as_float((unsigned)(u_[j_] & 0xffffffffull)); \
            part[((LTOK)*NP + 2*j_+1)*32 + slot_] = __uint_as_float((unsigned)(u_[j_] >> 32));           \
        }                                                                             \
    }                                                                                 \
} while (0)

__global__ void __launch_bounds__(NTHREADS, 2)
kdtree_router_kernel(const float* __restrict__ x,
                     const float* __restrict__ mean,
                     const float* __restrict__ comp,
                     const float* __restrict__ cent,
                     float* __restrict__ out)
{
    extern __shared__ __align__(1024) char smem_c[];
    float* part    = (float*)(smem_c + PART_OFF);
    float* cent_s  = (float*)(smem_c + CENT_OFF);
    float* centn_s = (float*)(smem_c + CENTN_OFF);
    const uint32_t mb = smem_u32(smem_c + MBAR_OFF);
    const uint32_t xs = smem_u32(smem_c + XS_OFF);

    const int tid  = threadIdx.x;
    const int lane = tid & 31;
    const int warp = tid >> 5;
    const int bid  = blockIdx.x;
    const int nb   = (bid < BIGCTAS) ? (NUNITS / GRID + 1) : (NUNITS / GRID);  // 7 or 6
    const int nchunks = nb * CPU;

    if (tid == 0) {
        #pragma unroll
        for (int s = 0; s < STAGES; s++) {
            MBAR_INIT(mb + s * 8, 1);               // full: expect_tx arrive
            MBAR_INIT(mb + 24 + s * 8, CWARPS);     // empty: 8 warp arrivals
        }
    }
    __syncthreads();   // only CTA-wide barrier; producer free-runs from here

    if (warp == PROD_WARP) {
        // ======== producer: static schedule, 4 lanes x 8 KB concurrent copies ========
        int s = 0, f = 0;
        #pragma unroll 1
        for (int k = 0; k < nb; k++) {
            const char* ubase = (const char*)x
                + ((size_t)(bid + GRID * k) * UNIT_TOK * HD) * 4;
            #pragma unroll 1
            for (int ci = 0; ci < CPU; ci++) {
                if (lane < NSPLIT && f >= 1)
                    MBAR_WAIT(mb + 24 + s * 8, (f & 1) ^ 1);
                __syncwarp();
                if (lane == 0)
                    MBAR_EXPECT_TX(mb + s * 8, (uint32_t)STAGE_BYTES);
                __syncwarp();
                if (lane < NSPLIT)
                    bulk_g2s(xs + s * STAGE_BYTES + lane * SPLIT_BYTES,
                             ubase + (size_t)ci * STAGE_BYTES + lane * SPLIT_BYTES,
                             SPLIT_BYTES, mb + s * 8);
                if (++s == STAGES) { s = 0; f++; }
            }
        }
        return;
    }

    // ======================= consumers (warps 0..7) =======================
    for (int i = tid; i < PART_ROWS * 32; i += 256) part[i] = 0.f;  // zero slots
    for (int i = tid; i < NE * NP; i += 256) cent_s[i] = cent[i];
    CBAR();

    ulonglong2 cA[NP * 4];   // 512-col comp slice: 4 blocks of 128 cols per p
    {
        #pragma unroll
        for (int p = 0; p < NP; p++) {
            const ulonglong2* cp0 = (const ulonglong2*)(comp + (size_t)p * HD + warp * SLICE);
            #pragma unroll
            for (int b = 0; b < 4; b++)
                cA[p*4 + b] = __ldg(cp0 + b * 32 + lane);
        }
        const ulonglong2* mp = (const ulonglong2*)(mean + warp * SLICE);
        TOKEN_COMPUTE512(mp, UNIT_TOK);   // mean projection partials -> row 8
        if (tid < NE) {
            float s = 0.f;
            #pragma unroll
            for (int p = 0; p < NP; p++) { float c = cent_s[tid*NP + p]; s += c * c; }
            centn_s[tid] = s;
        }
    }
    CBAR();

    float mpj[NP];
    #pragma unroll
    for (int p = 0; p < NP; p++) {
        float v = part[(UNIT_TOK*NP + p)*32 + lane];
        #pragma unroll
        for (int o = 16; o > 0; o >>= 1)
            v += __shfl_xor_sync(0xffffffffu, v, o);
        mpj[p] = v;
    }

    float* out_idx = out;
    float* out_tp  = out + (size_t)NTOK * TK;
    float* out_pr  = out + 2 * (size_t)NTOK * TK;

    int s = 0, f = 0;
    #pragma unroll 1
    for (int cc = 0; cc < nchunks; cc++) {
        MBAR_WAIT(mb + s * 8, f & 1);

        const int ltok = (cc & (CPU - 1)) * STAGE_TOK;     // 0,2,4,6

        #pragma unroll
        for (int t = 0; t < STAGE_TOK; t++) {
            const ulonglong2* xp = (const ulonglong2*)
                (smem_c + XS_OFF + s * STAGE_BYTES + t * (HD*4) + warp * (SLICE*4));
            TOKEN_COMPUTE512(xp, ltok + t);
        }
        __syncwarp();
        if (lane == 0) MBAR_ARRIVE(mb + 24 + s * 8);
        if (++s == STAGES) { s = 0; f ^= 1; }

        if (ltok == UNIT_TOK - STAGE_TOK) {
            // ---- unit complete -> epilogue: warp w handles token w ----
            CBAR();
            const unsigned unit = bid + GRID * (cc / CPU);
            const unsigned tok  = unit * UNIT_TOK + warp;

            float pr[NP];
            #pragma unroll
            for (int p = 0; p < NP; p++) {
                float v = part[(warp*NP + p)*32 + lane];   // slots 16..31 are zero
                #pragma unroll
                for (int o = 16; o > 0; o >>= 1)
                    v += __shfl_xor_sync(0xffffffffu, v, o);
                pr[p] = v - mpj[p];
            }
            float pn = 0.f;
            #pragma unroll
            for (int p = 0; p < NP; p++) pn += pr[p] * pr[p];

            const int e0 = lane, e1 = lane + 32;
            float dot0 = 0.f, dot1 = 0.f;
            #pragma unroll
            for (int p = 0; p < NP; p++) {
                dot0 += pr[p] * cent_s[e0*NP + p];
                dot1 += pr[p] * cent_s[e1*NP + p];
            }
            float d20 = pn - 2.f*dot0 + centn_s[e0];
            float d21 = pn - 2.f*dot1 + centn_s[e1];
            float s0 = -sqrtf(fmaxf(d20, 0.f));
            float s1 = -sqrtf(fmaxf(d21, 0.f));

            float m = fmaxf(s0, s1);
            #pragma unroll
            for (int o = 16; o > 0; o >>= 1)
                m = fmaxf(m, __shfl_xor_sync(0xffffffffu, m, o));
            float ex0 = expf(s0 - m);
            float ex1 = expf(s1 - m);
            float sum = ex0 + ex1;
            #pragma unroll
            for (int o = 16; o > 0; o >>= 1)
                sum += __shfl_xor_sync(0xffffffffu, sum, o);
            float p0 = ex0 / sum;
            float p1 = ex1 / sum;

            out_pr[(size_t)tok*NE + e0] = p0;
            out_pr[(size_t)tok*NE + e1] = p1;

            // top-8 via 8-round warp argmax; tie-break = lower index (jax.lax.top_k)
            unsigned long long k0 = ((unsigned long long)__float_as_uint(p0) << 32) | (unsigned)(NE-1 - e0);
            unsigned long long k1 = ((unsigned long long)__float_as_uint(p1) << 32) | (unsigned)(NE-1 - e1);
            float tsum = 0.f, myp = 0.f;
            int myi = 0;
            #pragma unroll
            for (int r = 0; r < TK; r++) {
                unsigned long long b = (k0 > k1) ? k0 : k1;
                #pragma unroll
                for (int o = 16; o > 0; o >>= 1) {
                    unsigned long long v = __shfl_xor_sync(0xffffffffu, b, o);
                    if (v > b) b = v;
                }
                int idx = NE-1 - (int)(b & 0xffull);
                float pv = __uint_as_float((unsigned)(b >> 32));
                tsum += pv;
                if (lane == r) { myp = pv; myi = idx; }
                if (idx == e0) k0 = 0ull;
                if (idx == e1) k1 = 0ull;
            }
            if (lane < TK) {
                out_idx[(size_t)tok*TK + lane] = (float)myi;
                out_tp [(size_t)tok*TK + lane] = myp / tsum;
            }
            CBAR();   // protect part[] before next unit overwrites
        }
    }
}

extern "C" void kernel_launch(void* const* d_in, const int* in_sizes, int n_in,
                              void* d_out, int out_size)
{
    const float* x    = (const float*)d_in[0];
    const float* mean = (const float*)d_in[1];
    const float* comp = (const float*)d_in[2];
    const float* cent = (const float*)d_in[3];
    float* out = (float*)d_out;

    cudaFuncSetAttribute(kdtree_router_kernel,
                         cudaFuncAttributeMaxDynamicSharedMemorySize, SMEM_BYTES);
    kdtree_router_kernel<<<GRID, NTHREADS, SMEM_BYTES>>>(x, mean, comp, cent, out);
}